// round 11
// baseline (speedup 1.0000x reference)
#include <cuda_runtime.h>
#include <cuda_fp16.h>
#include <cstdint>
#include <cstddef>

// ---------------- problem constants ----------------
#define B_ROWS 16384
#define F_CAT  26
#define N_NUM  13
#define VOCAB  100000
#define K1     1248
#define K1P    1280   // padded: 40 features x 32 dims (39 real + 1 pad)
#define H1     256
#define H2     128
#define H3     64

// ---------------- scratch (static device memory): weights only -------------
constexpr size_t ALN(size_t x) { return (x + 255) & ~(size_t)255; }
constexpr size_t OFF_W1T = 0;                                     // [256][1280] fp16
constexpr size_t OFF_W2T = ALN(OFF_W1T + (size_t)H1 * K1P * 2);   // [128][256]
constexpr size_t OFF_W3T = ALN(OFF_W2T + (size_t)H2 * H1 * 2);    // [64][128]
constexpr size_t TOTAL_SCRATCH = ALN(OFF_W3T + (size_t)H3 * H2 * 2);
__device__ __align__(256) unsigned char g_scratch[TOTAL_SCRATCH];

// ---------------- smem layout (bytes) ----------------
// mainloop: 3 stages x (A 128x144 + B 256x144) = 165888 at offset 0
#define ROWB      144
#define A_BYTES   (128 * ROWB)            // 18432
#define STAGE     ((128 + 256) * ROWB)    // 55296
#define SM_IDS    165888                  // int   [128][26] = 13312
#define SM_XNUM   179200                  // float [128][13] = 6656
#define SM_NEMB   185856                  // float [13][32]  = 1664
// post-mainloop reuse:
#define SM_H1     0                       // h1 [128][264 halves] stride 528
#define SM_W2     69632                   // W2' [128][264 halves] stride 528
#define SM_H2     139264                  // h2 [128][136 halves] stride 272
#define SM_W3     174336                  // W3' [64][136 halves] stride 272
#define SM_H3     192000                  // h3 [128][68 floats]  stride 272
#define SM_HEAD   226816                  // Wc(66 f32) | Wo(66 f32)
#define SM_LINP   227344                  // float [128][2]
#define SM_FMP    229392                  // float [128][2]
#define SMEM_MEGA 231440

// ---------------- PTX helpers (sm_80-compatible; no 'a' features) ----------
__device__ __forceinline__ uint32_t smem_to_u32(const void* p) {
    uint32_t a;
    asm("{ .reg .u64 t; cvta.to.shared.u64 t, %1; cvt.u32.u64 %0, t; }" : "=r"(a) : "l"(p));
    return a;
}
__device__ __forceinline__ void cp_async16(uint32_t saddr, const void* gaddr) {
    asm volatile("cp.async.cg.shared.global [%0], [%1], 16;"
                 :: "r"(saddr), "l"(gaddr) : "memory");
}
__device__ __forceinline__ void cp_commit() {
    asm volatile("cp.async.commit_group;" ::: "memory");
}
template<int N>
__device__ __forceinline__ void cp_wait() {
    asm volatile("cp.async.wait_group %0;" :: "n"(N) : "memory");
}
__device__ __forceinline__ void ldsm_x4(uint32_t& r0, uint32_t& r1,
                                        uint32_t& r2, uint32_t& r3, uint32_t addr) {
    asm volatile("ldmatrix.sync.aligned.m8n8.x4.shared.b16 {%0,%1,%2,%3}, [%4];"
                 : "=r"(r0), "=r"(r1), "=r"(r2), "=r"(r3) : "r"(addr));
}
__device__ __forceinline__ void mma16816(float* d, const uint32_t* a, const uint32_t* b) {
    asm volatile(
        "mma.sync.aligned.m16n8k16.row.col.f32.f16.f16.f32 "
        "{%0,%1,%2,%3}, {%4,%5,%6,%7}, {%8,%9}, {%0,%1,%2,%3};"
        : "+f"(d[0]), "+f"(d[1]), "+f"(d[2]), "+f"(d[3])
        : "r"(a[0]), "r"(a[1]), "r"(a[2]), "r"(a[3]), "r"(b[0]), "r"(b[1]));
}

// ---------------- prep: coalesced transposed fp16 weight tiles --------------
__global__ void prep_all(const float* __restrict__ W1, __half* __restrict__ o1,
                         const float* __restrict__ W2, __half* __restrict__ o2,
                         const float* __restrict__ W3, __half* __restrict__ o3)
{
    __shared__ __half t[32][72];
    int b = blockIdx.x;
    const float* W; __half* o; int K, N, ldw, tn, tc;
    if (b < 160)      {          W = W1; o = o1; K = K1; N = H1; ldw = K1P; tn = b % 8; tc = b / 8; }
    else if (b < 176) { b -= 160; W = W2; o = o2; K = H1; N = H2; ldw = H1;  tn = b % 4; tc = b / 4; }
    else              { b -= 176; W = W3; o = o3; K = H2; N = H3; ldw = H2;  tn = b % 2; tc = b / 2; }
    const int n0 = tn * 32, c0 = tc * 64;
    const int lx = threadIdx.x & 31, ly = threadIdx.x >> 5;
    #pragma unroll
    for (int cc = ly; cc < 64; cc += 8) {
        int c = c0 + cc;
        float v = (c < K) ? W[(size_t)c * N + n0 + lx] : 0.0f;
        t[lx][cc] = __float2half(v);
    }
    __syncthreads();
    const int rn = threadIdx.x >> 3;
    const int rc = (threadIdx.x & 7) * 8;
    *reinterpret_cast<uint4*>(o + (size_t)(n0 + rn) * ldw + c0 + rc) =
        *reinterpret_cast<const uint4*>(&t[rn][rc]);
}

// 16 fp16 values packed (one feature, 16 dims for this thread)
struct P16 { uint4 a, b; };

// ---------------- megakernel: gather + FM + full MLP + head ----------------
// 256 threads (8 warps). Mainloop warp grid 2x4, warp tile 64x64.
__global__ __launch_bounds__(256, 1)
void mega_mlp(const int*   __restrict__ x_cat,
              const float* __restrict__ x_num,
              const float* __restrict__ emb0,
              const float* __restrict__ emb1,
              const float* __restrict__ num_bias,
              const float* __restrict__ num_emb,
              const __half* __restrict__ w1t,
              const __half* __restrict__ w2t,
              const __half* __restrict__ w3t,
              const float* __restrict__ b1,
              const float* __restrict__ b2,
              const float* __restrict__ b3,
              const float* __restrict__ Wc, const float* __restrict__ bc,
              const float* __restrict__ Wo, const float* __restrict__ bo,
              float* __restrict__ out)
{
    constexpr int THREADS = 256;
    constexpr int lda     = K1P;
    constexpr int nchunks = K1P / 64;          // 20 (2 features per chunk)

    extern __shared__ unsigned char smem[];
    const uint32_t sbase = smem_to_u32(smem);

    const int tid = threadIdx.x;
    const int wid = tid >> 5;
    const int lid = tid & 31;
    const int mrow0 = blockIdx.y * 128;

    int*   s_ids  = reinterpret_cast<int*>(smem + SM_IDS);
    float* s_xnum = reinterpret_cast<float*>(smem + SM_XNUM);
    float* s_nemb = reinterpret_cast<float*>(smem + SM_NEMB);
    float* s_linp = reinterpret_cast<float*>(smem + SM_LINP);
    float* s_fmp  = reinterpret_cast<float*>(smem + SM_FMP);

    // ---------- B (W1') pipeline: 256 threads cover 32 rows/pass ----------
    const int b_r = tid >> 3, b_c = tid & 7;   // row, 16B chunk
    const uint32_t bsm_off = (uint32_t)b_r * ROWB + (uint32_t)b_c * 16;
    const __half* wrow = w1t + (size_t)b_r * lda + b_c * 8;
    auto issue_B = [&](int c, int buf) {
        const int kc = c * 64;
        uint32_t Bs = sbase + buf * STAGE + A_BYTES;
        #pragma unroll
        for (int i = 0; i < 8; i++)
            cp_async16(Bs + bsm_off + i * 32 * ROWB, wrow + (size_t)i * 32 * lda + kc);
    };

    // ---------- A gather: r = tid>>1 (128 rows), q = tid&1 (16 dims each) ---
    const int g_r = tid >> 1;
    const int g_q = tid & 1;

    // FM accumulators: this thread sees ALL features at its 16 d-positions
    float fmsum[16];
    #pragma unroll
    for (int i = 0; i < 16; i++) fmsum[i] = 0.0f;
    float sqtot = 0.0f;

    // fetch feature f (16 dims), accumulate FM, pack to fp16
    auto fetch_pack = [&](int f) -> P16 {
        float4 v[4];
        if (f < F_CAT) {
            int id = s_ids[g_r * F_CAT + f];
            const float4* p = reinterpret_cast<const float4*>(
                emb1 + ((size_t)f * VOCAB + id) * 32 + g_q * 16);
            v[0] = p[0]; v[1] = p[1]; v[2] = p[2]; v[3] = p[3];
        } else if (f < F_CAT + N_NUM) {
            int n = f - F_CAT;
            float xv = s_xnum[g_r * N_NUM + n];
            const float4* p = reinterpret_cast<const float4*>(s_nemb + n * 32 + g_q * 16);
            #pragma unroll
            for (int i = 0; i < 4; i++) {
                float4 e = p[i];
                v[i] = make_float4(xv * e.x, xv * e.y, xv * e.z, xv * e.w);
            }
        } else {
            #pragma unroll
            for (int i = 0; i < 4; i++) v[i] = make_float4(0, 0, 0, 0);
        }
        P16 r;
        uint32_t* ru = reinterpret_cast<uint32_t*>(&r);
        #pragma unroll
        for (int i = 0; i < 4; i++) {
            fmsum[i * 4 + 0] += v[i].x; fmsum[i * 4 + 1] += v[i].y;
            fmsum[i * 4 + 2] += v[i].z; fmsum[i * 4 + 3] += v[i].w;
            sqtot += v[i].x * v[i].x + v[i].y * v[i].y
                   + v[i].z * v[i].z + v[i].w * v[i].w;
            __half2 h0 = __floats2half2_rn(v[i].x, v[i].y);
            __half2 h1 = __floats2half2_rn(v[i].z, v[i].w);
            ru[i * 2 + 0] = *reinterpret_cast<uint32_t*>(&h0);
            ru[i * 2 + 1] = *reinterpret_cast<uint32_t*>(&h1);
        }
        return r;
    };
    auto store_pack = [&](const P16& p, int buf, int half) {
        unsigned char* dst = smem + buf * STAGE + g_r * ROWB + half * 64 + g_q * 32;
        *reinterpret_cast<uint4*>(dst)      = p.a;
        *reinterpret_cast<uint4*>(dst + 16) = p.b;
    };

    // ---------- prologue ----------
    issue_B(0, 0); cp_commit();
    issue_B(1, 1); cp_commit();

    for (int i = tid; i < 128 * F_CAT; i += THREADS)
        s_ids[i] = x_cat[(size_t)(mrow0 + i / F_CAT) * F_CAT + (i % F_CAT)];
    for (int i = tid; i < 128 * N_NUM; i += THREADS)
        s_xnum[i] = x_num[(size_t)(mrow0 + i / N_NUM) * N_NUM + (i % N_NUM)];
    for (int i = tid; i < N_NUM * 32; i += THREADS)
        s_nemb[i] = num_emb[i];
    __syncthreads();

    // linear-term partials (2 per row)
    {
        float lp = 0.0f;
        for (int f = g_q; f < F_CAT; f += 2)
            lp += __ldg(emb0 + (size_t)f * VOCAB + s_ids[g_r * F_CAT + f]);
        if (g_q == 0) {
            #pragma unroll
            for (int n = 0; n < N_NUM; n++)
                lp += s_xnum[g_r * N_NUM + n] * __ldg(num_bias + n);
        }
        s_linp[g_r * 2 + g_q] = lp;
    }
    // stage A chunks 0 and 1 (features 0..3)
    {
        P16 p0 = fetch_pack(0), p1 = fetch_pack(1);
        store_pack(p0, 0, 0); store_pack(p1, 0, 1);
        P16 p2 = fetch_pack(2), p3 = fetch_pack(3);
        store_pack(p2, 1, 0); store_pack(p3, 1, 1);
    }
    __syncthreads();

    // ---------- mainloop: warp grid 2x4, warp tile 64x64 ----------
    float acc[4][8][4];
    #pragma unroll
    for (int i = 0; i < 4; i++)
        #pragma unroll
        for (int j = 0; j < 8; j++)
            #pragma unroll
            for (int k = 0; k < 4; k++) acc[i][j][k] = 0.0f;

    const int wm = wid >> 2;                   // 0..1 (64 rows each)
    const int wn = wid & 3;                    // 0..3 (64 cols each)
    const uint32_t a_lane = (uint32_t)(wm * 64 + (lid & 15)) * ROWB + (uint32_t)(lid >> 4) * 16;
    const uint32_t b_lane = (uint32_t)(wn * 64 + (lid & 15)) * ROWB + (uint32_t)(lid >> 4) * 16;

    for (int c = 0; c < nchunks; c++) {
        const int buf = c % 3;
        cp_wait<1>();
        __syncthreads();

        const bool has = (c + 2 < nchunks);
        const int nbuf = (c + 2) % 3;
        if (has) issue_B(c + 2, nbuf);
        cp_commit();

        // fetch (LDG) before MMA block; store (STS) after -> latency hidden
        P16 p0, p1;
        if (has) { p0 = fetch_pack(2 * (c + 2)); p1 = fetch_pack(2 * (c + 2) + 1); }

        const uint32_t As = sbase + buf * STAGE + a_lane;
        const uint32_t Bs = sbase + buf * STAGE + A_BYTES + b_lane;
        #pragma unroll
        for (int kk = 0; kk < 4; kk++) {
            uint32_t bf_[8][2];
            #pragma unroll
            for (int j = 0; j < 4; j++) {
                uint32_t r0, r1, r2, r3;
                ldsm_x4(r0, r1, r2, r3, Bs + j * 16 * ROWB + kk * 32);
                bf_[j * 2 + 0][0] = r0; bf_[j * 2 + 0][1] = r2;
                bf_[j * 2 + 1][0] = r1; bf_[j * 2 + 1][1] = r3;
            }
            uint32_t af[4][4];
            #pragma unroll
            for (int mi = 0; mi < 4; mi++)
                ldsm_x4(af[mi][0], af[mi][1], af[mi][2], af[mi][3],
                        As + mi * 16 * ROWB + kk * 32);
            #pragma unroll
            for (int mi = 0; mi < 4; mi++)
                #pragma unroll
                for (int ni = 0; ni < 8; ni++)
                    mma16816(acc[mi][ni], af[mi], bf_[ni]);
        }

        if (has) { store_pack(p0, nbuf, 0); store_pack(p1, nbuf, 1); }
    }

    // FM partials (2 per row)
    {
        float p = -sqtot;
        #pragma unroll
        for (int j = 0; j < 16; j++) p += fmsum[j] * fmsum[j];
        s_fmp[g_r * 2 + g_q] = p;
    }

    cp_wait<0>();
    __syncthreads();

    // prefetch W2' (128x256 -> stride 528) and W3' (64x128 -> stride 272)
    {
        #pragma unroll
        for (int i = 0; i < 16; i++) {
            int idx = tid + i * THREADS;               // 4096 chunks
            int row = idx >> 5, ch = idx & 31;
            cp_async16(sbase + SM_W2 + row * 528 + ch * 16,
                       w2t + (size_t)row * H1 + ch * 8);
        }
        #pragma unroll
        for (int i = 0; i < 4; i++) {
            int idx = tid + i * THREADS;               // 1024 chunks
            int row = idx >> 4, ch = idx & 15;
            cp_async16(sbase + SM_W3 + row * 272 + ch * 16,
                       w3t + (size_t)row * H2 + ch * 8);
        }
        cp_commit();
    }
    {
        float* hw = reinterpret_cast<float*>(smem + SM_HEAD);
        if (tid < 66) { hw[tid] = Wc[tid]; hw[66 + tid] = Wo[tid]; }
    }

    // h1 fragments -> smem (relu + b1)
    {
        __half* h1p = reinterpret_cast<__half*>(smem + SM_H1);
        #pragma unroll
        for (int mi = 0; mi < 4; mi++) {
            #pragma unroll
            for (int ni = 0; ni < 8; ni++) {
                const int m0 = wm * 64 + mi * 16 + (lid >> 2);
                const int n0 = wn * 64 + ni * 8 + (lid & 3) * 2;
                const float c0 = __ldg(&b1[n0]);
                const float c1 = __ldg(&b1[n0 + 1]);
                __half2 p0, p1;
                p0.x = __float2half(fmaxf(acc[mi][ni][0] + c0, 0.0f));
                p0.y = __float2half(fmaxf(acc[mi][ni][1] + c1, 0.0f));
                p1.x = __float2half(fmaxf(acc[mi][ni][2] + c0, 0.0f));
                p1.y = __float2half(fmaxf(acc[mi][ni][3] + c1, 0.0f));
                *reinterpret_cast<__half2*>(&h1p[m0 * 264 + n0]) = p0;
                *reinterpret_cast<__half2*>(&h1p[(m0 + 8) * 264 + n0]) = p1;
            }
        }
    }
    cp_wait<0>();
    __syncthreads();

    // ---------- stage 2: h2 = relu(h1 @ W2 + b2), K=256; warp tile 64x32 ----
    {
        const int wm2 = wid >> 2;              // 0..1, 64 rows
        const int wn2 = wid & 3;               // 0..3, 32 cols
        const uint32_t a2 = sbase + SM_H1 +
            (uint32_t)(wm2 * 64 + (lid & 15)) * 528 + (uint32_t)(lid >> 4) * 16;
        const uint32_t b2s = sbase + SM_W2 +
            (uint32_t)(wn2 * 32 + (lid & 15)) * 528 + (uint32_t)(lid >> 4) * 16;

        float acc2[4][4][4];
        #pragma unroll
        for (int i = 0; i < 4; i++)
            #pragma unroll
            for (int j = 0; j < 4; j++)
                #pragma unroll
                for (int k = 0; k < 4; k++) acc2[i][j][k] = 0.0f;

        #pragma unroll
        for (int kk = 0; kk < 16; kk++) {
            uint32_t bf_[4][2];
            #pragma unroll
            for (int j = 0; j < 2; j++) {
                uint32_t r0, r1, r2, r3;
                ldsm_x4(r0, r1, r2, r3, b2s + j * 16 * 528 + kk * 32);
                bf_[j * 2 + 0][0] = r0; bf_[j * 2 + 0][1] = r2;
                bf_[j * 2 + 1][0] = r1; bf_[j * 2 + 1][1] = r3;
            }
            #pragma unroll
            for (int mi = 0; mi < 4; mi++) {
                uint32_t af[4];
                ldsm_x4(af[0], af[1], af[2], af[3], a2 + mi * 16 * 528 + kk * 32);
                #pragma unroll
                for (int ni = 0; ni < 4; ni++)
                    mma16816(acc2[mi][ni], af, bf_[ni]);
            }
        }

        __half* h2p = reinterpret_cast<__half*>(smem + SM_H2);
        #pragma unroll
        for (int mi = 0; mi < 4; mi++) {
            #pragma unroll
            for (int ni = 0; ni < 4; ni++) {
                const int m0 = wm2 * 64 + mi * 16 + (lid >> 2);
                const int n0 = wn2 * 32 + ni * 8 + (lid & 3) * 2;
                const float c0 = __ldg(&b2[n0]);
                const float c1 = __ldg(&b2[n0 + 1]);
                __half2 p0, p1;
                p0.x = __float2half(fmaxf(acc2[mi][ni][0] + c0, 0.0f));
                p0.y = __float2half(fmaxf(acc2[mi][ni][1] + c1, 0.0f));
                p1.x = __float2half(fmaxf(acc2[mi][ni][2] + c0, 0.0f));
                p1.y = __float2half(fmaxf(acc2[mi][ni][3] + c1, 0.0f));
                *reinterpret_cast<__half2*>(&h2p[m0 * 136 + n0]) = p0;
                *reinterpret_cast<__half2*>(&h2p[(m0 + 8) * 136 + n0]) = p1;
            }
        }
    }
    __syncthreads();

    // ---------- stage 3: h3 = relu(h2 @ W3 + b3), K=128; warp tile 32x32 ----
    {
        const int wm3 = wid >> 1;              // 0..3, 32 rows
        const int wn3 = wid & 1;               // 0..1, 32 cols
        const uint32_t a3 = sbase + SM_H2 +
            (uint32_t)(wm3 * 32 + (lid & 15)) * 272 + (uint32_t)(lid >> 4) * 16;
        const uint32_t b3s = sbase + SM_W3 +
            (uint32_t)(wn3 * 32 + (lid & 15)) * 272 + (uint32_t)(lid >> 4) * 16;

        float acc3[2][4][4];
        #pragma unroll
        for (int i = 0; i < 2; i++)
            #pragma unroll
            for (int j = 0; j < 4; j++)
                #pragma unroll
                for (int k = 0; k < 4; k++) acc3[i][j][k] = 0.0f;

        #pragma unroll
        for (int kk = 0; kk < 8; kk++) {
            uint32_t bf_[4][2];
            #pragma unroll
            for (int j = 0; j < 2; j++) {
                uint32_t r0, r1, r2, r3;
                ldsm_x4(r0, r1, r2, r3, b3s + j * 16 * 272 + kk * 32);
                bf_[j * 2 + 0][0] = r0; bf_[j * 2 + 0][1] = r2;
                bf_[j * 2 + 1][0] = r1; bf_[j * 2 + 1][1] = r3;
            }
            #pragma unroll
            for (int mi = 0; mi < 2; mi++) {
                uint32_t af[4];
                ldsm_x4(af[0], af[1], af[2], af[3], a3 + mi * 16 * 272 + kk * 32);
                #pragma unroll
                for (int ni = 0; ni < 4; ni++)
                    mma16816(acc3[mi][ni], af, bf_[ni]);
            }
        }

        float* h3p = reinterpret_cast<float*>(smem + SM_H3);
        #pragma unroll
        for (int mi = 0; mi < 2; mi++) {
            #pragma unroll
            for (int ni = 0; ni < 4; ni++) {
                const int m0 = wm3 * 32 + mi * 16 + (lid >> 2);
                const int n0 = wn3 * 32 + ni * 8 + (lid & 3) * 2;
                const float c0 = __ldg(&b3[n0]);
                const float c1 = __ldg(&b3[n0 + 1]);
                *reinterpret_cast<float2*>(&h3p[m0 * 68 + n0]) = make_float2(
                    fmaxf(acc3[mi][ni][0] + c0, 0.0f), fmaxf(acc3[mi][ni][1] + c1, 0.0f));
                *reinterpret_cast<float2*>(&h3p[(m0 + 8) * 68 + n0]) = make_float2(
                    fmaxf(acc3[mi][ni][2] + c0, 0.0f), fmaxf(acc3[mi][ni][3] + c1, 0.0f));
            }
        }
    }
    __syncthreads();

    // ---------- head ----------
    if (tid < 128) {
        const float* h3p = reinterpret_cast<const float*>(smem + SM_H3) + tid * 68;
        const float* hw  = reinterpret_cast<const float*>(smem + SM_HEAD);
        float dc = 0.0f, dw = 0.0f;
        #pragma unroll
        for (int c = 0; c < H3; c++) {
            float v = h3p[c];
            dc += v * hw[c];
            dw += v * hw[66 + c];
        }
        const float l = s_linp[tid * 2] + s_linp[tid * 2 + 1];
        const float f = 0.5f * (s_fmp[tid * 2] + s_fmp[tid * 2 + 1]);
        const int r = mrow0 + tid;
        out[r]          = dc + l * hw[64] + f * hw[65] + __ldg(&bc[0]);
        out[B_ROWS + r] = dw + l * hw[66 + 64] + f * hw[66 + 65] + __ldg(&bo[0]);
    }
}

// ---------------- launch ----------------
extern "C" void kernel_launch(void* const* d_in, const int* in_sizes, int n_in,
                              void* d_out, int out_size)
{
    const int*   x_cat    = (const int*)  d_in[0];
    const float* x_num    = (const float*)d_in[1];
    const float* emb0     = (const float*)d_in[2];
    const float* emb1     = (const float*)d_in[3];
    const float* num_bias = (const float*)d_in[4];
    const float* num_emb  = (const float*)d_in[5];
    const float* W1 = (const float*)d_in[6];
    const float* b1 = (const float*)d_in[7];
    const float* W2 = (const float*)d_in[8];
    const float* b2 = (const float*)d_in[9];
    const float* W3 = (const float*)d_in[10];
    const float* b3 = (const float*)d_in[11];
    const float* Wc = (const float*)d_in[12];
    const float* bc = (const float*)d_in[13];
    const float* Wo = (const float*)d_in[14];
    const float* bo = (const float*)d_in[15];
    float* out = (float*)d_out;

    unsigned char* base = nullptr;
    cudaGetSymbolAddress((void**)&base, g_scratch);
    __half* w1t = (__half*)(base + OFF_W1T);
    __half* w2t = (__half*)(base + OFF_W2T);
    __half* w3t = (__half*)(base + OFF_W3T);

    cudaFuncSetAttribute(mega_mlp,
                         cudaFuncAttributeMaxDynamicSharedMemorySize, SMEM_MEGA);

    // 0) weight prep: 160 + 16 + 4 transpose tiles (coalesced)
    prep_all<<<180, 256>>>(W1, w1t, W2, w2t, W3, w3t);

    // 1) fused gather + FM + MLP + head
    mega_mlp<<<dim3(1, B_ROWS / 128), 256, SMEM_MEGA>>>(
        x_cat, x_num, emb0, emb1, num_bias, num_emb,
        w1t, w2t, w3t, b1, b2, b3, Wc, bc, Wo, bo, out);
}

// round 12
// speedup vs baseline: 1.1511x; 1.1511x over previous
#include <cuda_runtime.h>
#include <cuda_fp16.h>
#include <cstdint>
#include <cstddef>

// ---------------- problem constants ----------------
#define B_ROWS 16384
#define F_CAT  26
#define N_NUM  13
#define VOCAB  100000
#define K1     1248
#define K1P    1280   // padded: 40 features x 32 dims (39 real + 1 pad)
#define H1     256
#define H2     128
#define H3     64

// ---------------- scratch (static device memory): weights only -------------
constexpr size_t ALN(size_t x) { return (x + 255) & ~(size_t)255; }
constexpr size_t OFF_W1T = 0;                                     // [256][1280] fp16
constexpr size_t OFF_W2T = ALN(OFF_W1T + (size_t)H1 * K1P * 2);   // [128][256]
constexpr size_t OFF_W3T = ALN(OFF_W2T + (size_t)H2 * H1 * 2);    // [64][128]
constexpr size_t TOTAL_SCRATCH = ALN(OFF_W3T + (size_t)H3 * H2 * 2);
__device__ __align__(256) unsigned char g_scratch[TOTAL_SCRATCH];

// ---------------- smem layout (bytes) ----------------
// mainloop: 3 stages x (A 128x144 + B 256x144) = 165888 at offset 0
#define ROWB      144
#define A_BYTES   (128 * ROWB)            // 18432
#define STAGE     ((128 + 256) * ROWB)    // 55296
#define SM_IDS    165888                  // int   [128][26] = 13312
#define SM_XNUM   179200                  // float [128][13] = 6656
#define SM_NEMB   185856                  // float [13][32]  = 1664
// post-mainloop reuse:
#define SM_H1     0                       // h1 [128][264 halves] stride 528
#define SM_W2     69632                   // W2' [128][264 halves] stride 528
#define SM_H2     139264                  // h2 [128][136 halves] stride 272
#define SM_W3     174336                  // W3' [64][136 halves] stride 272
#define SM_H3     192000                  // h3 [128][68 floats]  stride 272
#define SM_HEAD   226816                  // Wc(66 f32) | Wo(66 f32)
#define SM_LINP   227344                  // float [128][4]
#define SM_FMP    229392                  // float [128][4]
#define SMEM_MEGA 231440

// ---------------- PTX helpers (sm_80-compatible; no 'a' features) ----------
__device__ __forceinline__ uint32_t smem_to_u32(const void* p) {
    uint32_t a;
    asm("{ .reg .u64 t; cvta.to.shared.u64 t, %1; cvt.u32.u64 %0, t; }" : "=r"(a) : "l"(p));
    return a;
}
__device__ __forceinline__ void cp_async16(uint32_t saddr, const void* gaddr) {
    asm volatile("cp.async.cg.shared.global [%0], [%1], 16;"
                 :: "r"(saddr), "l"(gaddr) : "memory");
}
__device__ __forceinline__ void cp_commit() {
    asm volatile("cp.async.commit_group;" ::: "memory");
}
template<int N>
__device__ __forceinline__ void cp_wait() {
    asm volatile("cp.async.wait_group %0;" :: "n"(N) : "memory");
}
__device__ __forceinline__ void ldsm_x4(uint32_t& r0, uint32_t& r1,
                                        uint32_t& r2, uint32_t& r3, uint32_t addr) {
    asm volatile("ldmatrix.sync.aligned.m8n8.x4.shared.b16 {%0,%1,%2,%3}, [%4];"
                 : "=r"(r0), "=r"(r1), "=r"(r2), "=r"(r3) : "r"(addr));
}
__device__ __forceinline__ void mma16816(float* d, const uint32_t* a, const uint32_t* b) {
    asm volatile(
        "mma.sync.aligned.m16n8k16.row.col.f32.f16.f16.f32 "
        "{%0,%1,%2,%3}, {%4,%5,%6,%7}, {%8,%9}, {%0,%1,%2,%3};"
        : "+f"(d[0]), "+f"(d[1]), "+f"(d[2]), "+f"(d[3])
        : "r"(a[0]), "r"(a[1]), "r"(a[2]), "r"(a[3]), "r"(b[0]), "r"(b[1]));
}

// ---------------- prep: coalesced transposed fp16 weight tiles --------------
// 32 n-rows x 64 k-cols per block via smem transpose. Grid decode:
//   W1: 8 x 20 = 160 tiles, W2: 4 x 4 = 16, W3: 2 x 2 = 4 -> 180 blocks
__global__ void prep_all(const float* __restrict__ W1, __half* __restrict__ o1,
                         const float* __restrict__ W2, __half* __restrict__ o2,
                         const float* __restrict__ W3, __half* __restrict__ o3)
{
    __shared__ __half t[32][72];   // 144B row stride, 16B-aligned rows
    int b = blockIdx.x;
    const float* W; __half* o; int K, N, ldw, tn, tc;
    if (b < 160)      {          W = W1; o = o1; K = K1; N = H1; ldw = K1P; tn = b % 8; tc = b / 8; }
    else if (b < 176) { b -= 160; W = W2; o = o2; K = H1; N = H2; ldw = H1;  tn = b % 4; tc = b / 4; }
    else              { b -= 176; W = W3; o = o3; K = H2; N = H3; ldw = H2;  tn = b % 2; tc = b / 2; }
    const int n0 = tn * 32, c0 = tc * 64;
    const int lx = threadIdx.x & 31, ly = threadIdx.x >> 5;  // 256 threads
    #pragma unroll
    for (int cc = ly; cc < 64; cc += 8) {
        int c = c0 + cc;
        float v = (c < K) ? W[(size_t)c * N + n0 + lx] : 0.0f;  // coalesced read
        t[lx][cc] = __float2half(v);
    }
    __syncthreads();
    const int rn = threadIdx.x >> 3;
    const int rc = (threadIdx.x & 7) * 8;
    *reinterpret_cast<uint4*>(o + (size_t)(n0 + rn) * ldw + c0 + rc) =
        *reinterpret_cast<const uint4*>(&t[rn][rc]);            // coalesced write
}

// 8 fp32 values of one feature at d in [q*8, q*8+8)
struct A8 { float4 a, b; };

// ---------------- megakernel: gather + FM + full MLP + head ----------------
// R9 configuration: 512 threads, mainloop warp grid 2x8, warp tile 64x32.
__global__ __launch_bounds__(512)
void mega_mlp(const int*   __restrict__ x_cat,
              const float* __restrict__ x_num,
              const float* __restrict__ emb0,
              const float* __restrict__ emb1,
              const float* __restrict__ num_bias,
              const float* __restrict__ num_emb,
              const __half* __restrict__ w1t,
              const __half* __restrict__ w2t,
              const __half* __restrict__ w3t,
              const float* __restrict__ b1,
              const float* __restrict__ b2,
              const float* __restrict__ b3,
              const float* __restrict__ Wc, const float* __restrict__ bc,
              const float* __restrict__ Wo, const float* __restrict__ bo,
              float* __restrict__ out)
{
    constexpr int THREADS = 512;
    constexpr int lda     = K1P;
    constexpr int nchunks = K1P / 64;          // 20 (2 features per chunk)

    extern __shared__ unsigned char smem[];
    const uint32_t sbase = smem_to_u32(smem);

    const int tid = threadIdx.x;
    const int wid = tid >> 5;
    const int lid = tid & 31;
    const int mrow0 = blockIdx.y * 128;

    int*   s_ids  = reinterpret_cast<int*>(smem + SM_IDS);
    float* s_xnum = reinterpret_cast<float*>(smem + SM_XNUM);
    float* s_nemb = reinterpret_cast<float*>(smem + SM_NEMB);
    float* s_linp = reinterpret_cast<float*>(smem + SM_LINP);
    float* s_fmp  = reinterpret_cast<float*>(smem + SM_FMP);

    // ---------- B (W1') pipeline ----------
    const int b_r = tid >> 3, b_c = tid & 7;   // row, 16B chunk
    const uint32_t bsm_off = (uint32_t)b_r * ROWB + (uint32_t)b_c * 16;
    const __half* wrow = w1t + (size_t)b_r * lda + b_c * 8;
    auto issue_B = [&](int c, int buf) {
        const int kc = c * 64;
        uint32_t Bs = sbase + buf * STAGE + A_BYTES;
        #pragma unroll
        for (int i = 0; i < 4; i++)
            cp_async16(Bs + bsm_off + i * 64 * ROWB, wrow + (size_t)i * 64 * lda + kc);
    };

    // ---------- A gather mapping: r = tid>>2 (128 rows), q = tid&3 ----------
    const int g_r = tid >> 2;
    const int g_q = tid & 3;

    // FM accumulators: this thread sees ALL features at its 8 d-positions
    float fmsum[8] = {0, 0, 0, 0, 0, 0, 0, 0};
    float sqtot = 0.0f;

    auto fetch_feat = [&](int f) -> A8 {
        A8 o;
        if (f < F_CAT) {
            int id = s_ids[g_r * F_CAT + f];
            const float4* p = reinterpret_cast<const float4*>(
                emb1 + ((size_t)f * VOCAB + id) * 32 + g_q * 8);
            o.a = p[0]; o.b = p[1];
        } else if (f < F_CAT + N_NUM) {
            int n = f - F_CAT;
            float xv = s_xnum[g_r * N_NUM + n];
            const float4* p = reinterpret_cast<const float4*>(s_nemb + n * 32 + g_q * 8);
            float4 e0 = p[0], e1 = p[1];
            o.a = make_float4(xv * e0.x, xv * e0.y, xv * e0.z, xv * e0.w);
            o.b = make_float4(xv * e1.x, xv * e1.y, xv * e1.z, xv * e1.w);
        } else {
            o.a = make_float4(0, 0, 0, 0);
            o.b = make_float4(0, 0, 0, 0);
        }
        return o;
    };
    // accumulate FM + convert + store 16B into A stage (half = 0 for f0, 1 for f1)
    auto store_feat = [&](const A8& v, int buf, int half) {
        fmsum[0] += v.a.x; fmsum[1] += v.a.y; fmsum[2] += v.a.z; fmsum[3] += v.a.w;
        fmsum[4] += v.b.x; fmsum[5] += v.b.y; fmsum[6] += v.b.z; fmsum[7] += v.b.w;
        sqtot += v.a.x * v.a.x + v.a.y * v.a.y + v.a.z * v.a.z + v.a.w * v.a.w
               + v.b.x * v.b.x + v.b.y * v.b.y + v.b.z * v.b.z + v.b.w * v.b.w;
        __half2 h0 = __floats2half2_rn(v.a.x, v.a.y);
        __half2 h1 = __floats2half2_rn(v.a.z, v.a.w);
        __half2 h2 = __floats2half2_rn(v.b.x, v.b.y);
        __half2 h3 = __floats2half2_rn(v.b.z, v.b.w);
        uint4 u;
        u.x = *reinterpret_cast<uint32_t*>(&h0);
        u.y = *reinterpret_cast<uint32_t*>(&h1);
        u.z = *reinterpret_cast<uint32_t*>(&h2);
        u.w = *reinterpret_cast<uint32_t*>(&h3);
        *reinterpret_cast<uint4*>(smem + buf * STAGE + g_r * ROWB + half * 64 + g_q * 16) = u;
    };

    // ---------- prologue ----------
    issue_B(0, 0); cp_commit();
    issue_B(1, 1); cp_commit();

    // preload ids / x_num / num_emb
    for (int i = tid; i < 128 * F_CAT; i += THREADS)
        s_ids[i] = x_cat[(size_t)(mrow0 + i / F_CAT) * F_CAT + (i % F_CAT)];
    for (int i = tid; i < 128 * N_NUM; i += THREADS)
        s_xnum[i] = x_num[(size_t)(mrow0 + i / N_NUM) * N_NUM + (i % N_NUM)];
    for (int i = tid; i < N_NUM * 32; i += THREADS)
        s_nemb[i] = num_emb[i];
    __syncthreads();

    // linear-term partials (4 per row)
    {
        float lp = 0.0f;
        for (int f = g_q; f < F_CAT; f += 4)
            lp += __ldg(emb0 + (size_t)f * VOCAB + s_ids[g_r * F_CAT + f]);
        if (g_q == 0) {
            #pragma unroll
            for (int n = 0; n < N_NUM; n++)
                lp += s_xnum[g_r * N_NUM + n] * __ldg(num_bias + n);
        }
        s_linp[g_r * 4 + g_q] = lp;
    }
    // stage A chunks 0 and 1
    {
        A8 v0 = fetch_feat(0), v1 = fetch_feat(1);
        store_feat(v0, 0, 0); store_feat(v1, 0, 1);
        A8 v2 = fetch_feat(2), v3 = fetch_feat(3);
        store_feat(v2, 1, 0); store_feat(v3, 1, 1);
    }
    __syncthreads();

    // ---------- mainloop: warp grid 2x8, warp tile 64x32 ----------
    float acc[4][4][4];
    #pragma unroll
    for (int i = 0; i < 4; i++)
        #pragma unroll
        for (int j = 0; j < 4; j++)
            #pragma unroll
            for (int k = 0; k < 4; k++) acc[i][j][k] = 0.0f;

    const int wm = wid >> 3;                   // 0..1
    const int wn = wid & 7;                    // 0..7
    const uint32_t a_lane = (uint32_t)(wm * 64 + (lid & 15)) * ROWB + (uint32_t)(lid >> 4) * 16;
    const uint32_t b_lane = (uint32_t)(wn * 32 + (lid & 15)) * ROWB + (uint32_t)(lid >> 4) * 16;

    for (int c = 0; c < nchunks; c++) {
        const int buf = c % 3;
        cp_wait<1>();
        __syncthreads();

        const bool has = (c + 2 < nchunks);
        const int nbuf = (c + 2) % 3;
        if (has) issue_B(c + 2, nbuf);
        cp_commit();

        A8 v0, v1;
        if (has) { v0 = fetch_feat(2 * (c + 2)); v1 = fetch_feat(2 * (c + 2) + 1); }

        const uint32_t As = sbase + buf * STAGE + a_lane;
        const uint32_t Bs = sbase + buf * STAGE + A_BYTES + b_lane;
        #pragma unroll
        for (int kk = 0; kk < 4; kk++) {
            uint32_t bf_[4][2];
            #pragma unroll
            for (int j = 0; j < 2; j++) {
                uint32_t r0, r1, r2, r3;
                ldsm_x4(r0, r1, r2, r3, Bs + j * 16 * ROWB + kk * 32);
                bf_[j * 2 + 0][0] = r0; bf_[j * 2 + 0][1] = r2;
                bf_[j * 2 + 1][0] = r1; bf_[j * 2 + 1][1] = r3;
            }
            uint32_t af[4][4];
            #pragma unroll
            for (int mi = 0; mi < 4; mi++)
                ldsm_x4(af[mi][0], af[mi][1], af[mi][2], af[mi][3],
                        As + mi * 16 * ROWB + kk * 32);
            #pragma unroll
            for (int mi = 0; mi < 4; mi++)
                #pragma unroll
                for (int ni = 0; ni < 4; ni++)
                    mma16816(acc[mi][ni], af[mi], bf_[ni]);
        }

        if (has) { store_feat(v0, nbuf, 0); store_feat(v1, nbuf, 1); }
    }

    // FM partials (all features seen; finalize per thread)
    {
        float p = -sqtot;
        #pragma unroll
        for (int j = 0; j < 8; j++) p += fmsum[j] * fmsum[j];
        s_fmp[g_r * 4 + g_q] = p;
    }

    cp_wait<0>();
    __syncthreads();

    // prefetch W2' (128 x 256 -> stride 528) and W3' (64 x 128 -> stride 272)
    {
        #pragma unroll
        for (int i = 0; i < 8; i++) {
            int idx = tid + i * THREADS;               // 4096 chunks
            int row = idx >> 5, ch = idx & 31;
            cp_async16(sbase + SM_W2 + row * 528 + ch * 16,
                       w2t + (size_t)row * H1 + ch * 8);
        }
        #pragma unroll
        for (int i = 0; i < 2; i++) {
            int idx = tid + i * THREADS;               // 1024 chunks
            int row = idx >> 4, ch = idx & 15;
            cp_async16(sbase + SM_W3 + row * 272 + ch * 16,
                       w3t + (size_t)row * H2 + ch * 8);
        }
        cp_commit();
    }
    {
        float* hw = reinterpret_cast<float*>(smem + SM_HEAD);
        if (tid < 66)  hw[tid] = Wc[tid];
        if (tid >= 256 && tid < 322) hw[66 + tid - 256] = Wo[tid - 256];
    }

    // h1 fragments -> smem (relu + b1)
    {
        __half* h1p = reinterpret_cast<__half*>(smem + SM_H1);
        #pragma unroll
        for (int mi = 0; mi < 4; mi++) {
            #pragma unroll
            for (int ni = 0; ni < 4; ni++) {
                const int m0 = wm * 64 + mi * 16 + (lid >> 2);
                const int n0 = wn * 32 + ni * 8 + (lid & 3) * 2;
                const float c0 = __ldg(&b1[n0]);
                const float c1 = __ldg(&b1[n0 + 1]);
                __half2 p0, p1;
                p0.x = __float2half(fmaxf(acc[mi][ni][0] + c0, 0.0f));
                p0.y = __float2half(fmaxf(acc[mi][ni][1] + c1, 0.0f));
                p1.x = __float2half(fmaxf(acc[mi][ni][2] + c0, 0.0f));
                p1.y = __float2half(fmaxf(acc[mi][ni][3] + c1, 0.0f));
                *reinterpret_cast<__half2*>(&h1p[m0 * 264 + n0]) = p0;
                *reinterpret_cast<__half2*>(&h1p[(m0 + 8) * 264 + n0]) = p1;
            }
        }
    }
    cp_wait<0>();
    __syncthreads();

    // ---------- stage 2: h2 = relu(h1 @ W2 + b2), K=256 ----------
    {
        const int wm2 = wid >> 3;
        const int wn2 = wid & 7;
        const uint32_t a2 = sbase + SM_H1 +
            (uint32_t)(wm2 * 64 + (lid & 15)) * 528 + (uint32_t)(lid >> 4) * 16;
        const uint32_t b2s = sbase + SM_W2 +
            (uint32_t)(wn2 * 16 + (lid & 15)) * 528 + (uint32_t)(lid >> 4) * 16;

        float acc2[4][2][4];
        #pragma unroll
        for (int i = 0; i < 4; i++)
            #pragma unroll
            for (int j = 0; j < 2; j++)
                #pragma unroll
                for (int k = 0; k < 4; k++) acc2[i][j][k] = 0.0f;

        #pragma unroll
        for (int kk = 0; kk < 16; kk++) {
            uint32_t r0, r1, r2, r3;
            ldsm_x4(r0, r1, r2, r3, b2s + kk * 32);
            uint32_t bf0[2] = {r0, r2};
            uint32_t bf1[2] = {r1, r3};
            #pragma unroll
            for (int mi = 0; mi < 4; mi++) {
                uint32_t af[4];
                ldsm_x4(af[0], af[1], af[2], af[3], a2 + mi * 16 * 528 + kk * 32);
                mma16816(acc2[mi][0], af, bf0);
                mma16816(acc2[mi][1], af, bf1);
            }
        }

        __half* h2p = reinterpret_cast<__half*>(smem + SM_H2);
        #pragma unroll
        for (int mi = 0; mi < 4; mi++) {
            #pragma unroll
            for (int ni = 0; ni < 2; ni++) {
                const int m0 = wm2 * 64 + mi * 16 + (lid >> 2);
                const int n0 = wn2 * 16 + ni * 8 + (lid & 3) * 2;
                const float c0 = __ldg(&b2[n0]);
                const float c1 = __ldg(&b2[n0 + 1]);
                __half2 p0, p1;
                p0.x = __float2half(fmaxf(acc2[mi][ni][0] + c0, 0.0f));
                p0.y = __float2half(fmaxf(acc2[mi][ni][1] + c1, 0.0f));
                p1.x = __float2half(fmaxf(acc2[mi][ni][2] + c0, 0.0f));
                p1.y = __float2half(fmaxf(acc2[mi][ni][3] + c1, 0.0f));
                *reinterpret_cast<__half2*>(&h2p[m0 * 136 + n0]) = p0;
                *reinterpret_cast<__half2*>(&h2p[(m0 + 8) * 136 + n0]) = p1;
            }
        }
    }
    __syncthreads();

    // ---------- stage 3: h3 = relu(h2 @ W3 + b3), K=128 ----------
    {
        const int wm3 = wid >> 2;
        const int wn3 = wid & 3;
        const uint32_t a3 = sbase + SM_H2 +
            (uint32_t)(wm3 * 32 + (lid & 15)) * 272 + (uint32_t)(lid >> 4) * 16;
        const uint32_t b3s = sbase + SM_W3 +
            (uint32_t)(wn3 * 16 + (lid & 15)) * 272 + (uint32_t)(lid >> 4) * 16;

        float acc3[2][2][4];
        #pragma unroll
        for (int i = 0; i < 2; i++)
            #pragma unroll
            for (int j = 0; j < 2; j++)
                #pragma unroll
                for (int k = 0; k < 4; k++) acc3[i][j][k] = 0.0f;

        #pragma unroll
        for (int kk = 0; kk < 8; kk++) {
            uint32_t r0, r1, r2, r3;
            ldsm_x4(r0, r1, r2, r3, b3s + kk * 32);
            uint32_t bf0[2] = {r0, r2};
            uint32_t bf1[2] = {r1, r3};
            #pragma unroll
            for (int mi = 0; mi < 2; mi++) {
                uint32_t af[4];
                ldsm_x4(af[0], af[1], af[2], af[3], a3 + mi * 16 * 272 + kk * 32);
                mma16816(acc3[mi][0], af, bf0);
                mma16816(acc3[mi][1], af, bf1);
            }
        }

        float* h3p = reinterpret_cast<float*>(smem + SM_H3);
        #pragma unroll
        for (int mi = 0; mi < 2; mi++) {
            #pragma unroll
            for (int ni = 0; ni < 2; ni++) {
                const int m0 = wm3 * 32 + mi * 16 + (lid >> 2);
                const int n0 = wn3 * 16 + ni * 8 + (lid & 3) * 2;
                const float c0 = __ldg(&b3[n0]);
                const float c1 = __ldg(&b3[n0 + 1]);
                *reinterpret_cast<float2*>(&h3p[m0 * 68 + n0]) = make_float2(
                    fmaxf(acc3[mi][ni][0] + c0, 0.0f), fmaxf(acc3[mi][ni][1] + c1, 0.0f));
                *reinterpret_cast<float2*>(&h3p[(m0 + 8) * 68 + n0]) = make_float2(
                    fmaxf(acc3[mi][ni][2] + c0, 0.0f), fmaxf(acc3[mi][ni][3] + c1, 0.0f));
            }
        }
    }
    __syncthreads();

    // ---------- head ----------
    if (tid < 128) {
        const float* h3p = reinterpret_cast<const float*>(smem + SM_H3) + tid * 68;
        const float* hw  = reinterpret_cast<const float*>(smem + SM_HEAD);
        float dc = 0.0f, dw = 0.0f;
        #pragma unroll
        for (int c = 0; c < H3; c++) {
            float v = h3p[c];
            dc += v * hw[c];
            dw += v * hw[66 + c];
        }
        const float l = s_linp[tid * 4] + s_linp[tid * 4 + 1]
                      + s_linp[tid * 4 + 2] + s_linp[tid * 4 + 3];
        const float f = 0.5f * (s_fmp[tid * 4] + s_fmp[tid * 4 + 1]
                              + s_fmp[tid * 4 + 2] + s_fmp[tid * 4 + 3]);
        const int r = mrow0 + tid;
        out[r]          = dc + l * hw[64] + f * hw[65] + __ldg(&bc[0]);
        out[B_ROWS + r] = dw + l * hw[66 + 64] + f * hw[66 + 65] + __ldg(&bo[0]);
    }
}

// ---------------- launch ----------------
extern "C" void kernel_launch(void* const* d_in, const int* in_sizes, int n_in,
                              void* d_out, int out_size)
{
    const int*   x_cat    = (const int*)  d_in[0];
    const float* x_num    = (const float*)d_in[1];
    const float* emb0     = (const float*)d_in[2];
    const float* emb1     = (const float*)d_in[3];
    const float* num_bias = (const float*)d_in[4];
    const float* num_emb  = (const float*)d_in[5];
    const float* W1 = (const float*)d_in[6];
    const float* b1 = (const float*)d_in[7];
    const float* W2 = (const float*)d_in[8];
    const float* b2 = (const float*)d_in[9];
    const float* W3 = (const float*)d_in[10];
    const float* b3 = (const float*)d_in[11];
    const float* Wc = (const float*)d_in[12];
    const float* bc = (const float*)d_in[13];
    const float* Wo = (const float*)d_in[14];
    const float* bo = (const float*)d_in[15];
    float* out = (float*)d_out;

    unsigned char* base = nullptr;
    cudaGetSymbolAddress((void**)&base, g_scratch);
    __half* w1t = (__half*)(base + OFF_W1T);
    __half* w2t = (__half*)(base + OFF_W2T);
    __half* w3t = (__half*)(base + OFF_W3T);

    cudaFuncSetAttribute(mega_mlp,
                         cudaFuncAttributeMaxDynamicSharedMemorySize, SMEM_MEGA);

    // 0) weight prep: 160 + 16 + 4 transpose tiles (coalesced)
    prep_all<<<180, 256>>>(W1, w1t, W2, w2t, W3, w3t);

    // 1) fused gather + FM + MLP + head
    mega_mlp<<<dim3(1, B_ROWS / 128), 512, SMEM_MEGA>>>(
        x_cat, x_num, emb0, emb1, num_bias, num_emb,
        w1t, w2t, w3t, b1, b2, b3, Wc, bc, Wo, bo, out);
}

// round 13
// speedup vs baseline: 1.1573x; 1.0053x over previous
#include <cuda_runtime.h>
#include <cuda_fp16.h>
#include <cstdint>
#include <cstddef>

// ---------------- problem constants ----------------
#define B_ROWS 16384
#define F_CAT  26
#define N_NUM  13
#define VOCAB  100000
#define K1     1248
#define K1P    1280   // padded: 40 features x 32 dims (39 real + 1 pad)
#define H1     256
#define H2     128
#define H3     64

// ---------------- scratch (static device memory): weights only -------------
constexpr size_t ALN(size_t x) { return (x + 255) & ~(size_t)255; }
constexpr size_t OFF_W1T = 0;                                     // [256][1280] fp16
constexpr size_t OFF_W2T = ALN(OFF_W1T + (size_t)H1 * K1P * 2);   // [128][256]
constexpr size_t OFF_W3T = ALN(OFF_W2T + (size_t)H2 * H1 * 2);    // [64][128]
constexpr size_t TOTAL_SCRATCH = ALN(OFF_W3T + (size_t)H3 * H2 * 2);
__device__ __align__(256) unsigned char g_scratch[TOTAL_SCRATCH];

// ---------------- smem layout (bytes) ----------------
// mainloop: 3 stages x (A 128x144 + B 256x144) = 165888 at offset 0
#define ROWB      144
#define A_BYTES   (128 * ROWB)            // 18432
#define STAGE     ((128 + 256) * ROWB)    // 55296
#define SM_IDS    165888                  // int   [128][26] = 13312
#define SM_XNUM   179200                  // float [128][13] = 6656
#define SM_NEMB   185856                  // float [13][32]  = 1664
// post-mainloop reuse:
#define SM_H1     0                       // h1 [128][264 halves] stride 528
#define SM_W2     69632                   // W2' [128][264 halves] stride 528
#define SM_H2     139264                  // h2 [128][136 halves] stride 272
#define SM_W3     174336                  // W3' [64][136 halves] stride 272
#define SM_H3     192000                  // h3 [128][68 floats]  stride 272
#define SM_HEAD   226816                  // Wc(66 f32) | Wo(66 f32)
#define SM_LINP   227344                  // float [128][4]
#define SM_FMP    229392                  // float [128][4]
#define SMEM_MEGA 231440

// ---------------- PTX helpers (sm_80-compatible; no 'a' features) ----------
__device__ __forceinline__ uint32_t smem_to_u32(const void* p) {
    uint32_t a;
    asm("{ .reg .u64 t; cvta.to.shared.u64 t, %1; cvt.u32.u64 %0, t; }" : "=r"(a) : "l"(p));
    return a;
}
__device__ __forceinline__ void cp_async16(uint32_t saddr, const void* gaddr) {
    asm volatile("cp.async.cg.shared.global [%0], [%1], 16;"
                 :: "r"(saddr), "l"(gaddr) : "memory");
}
__device__ __forceinline__ void cp_commit() {
    asm volatile("cp.async.commit_group;" ::: "memory");
}
template<int N>
__device__ __forceinline__ void cp_wait() {
    asm volatile("cp.async.wait_group %0;" :: "n"(N) : "memory");
}
__device__ __forceinline__ void ldsm_x4(uint32_t& r0, uint32_t& r1,
                                        uint32_t& r2, uint32_t& r3, uint32_t addr) {
    asm volatile("ldmatrix.sync.aligned.m8n8.x4.shared.b16 {%0,%1,%2,%3}, [%4];"
                 : "=r"(r0), "=r"(r1), "=r"(r2), "=r"(r3) : "r"(addr));
}
__device__ __forceinline__ void mma16816(float* d, const uint32_t* a, const uint32_t* b) {
    asm volatile(
        "mma.sync.aligned.m16n8k16.row.col.f32.f16.f16.f32 "
        "{%0,%1,%2,%3}, {%4,%5,%6,%7}, {%8,%9}, {%0,%1,%2,%3};"
        : "+f"(d[0]), "+f"(d[1]), "+f"(d[2]), "+f"(d[3])
        : "r"(a[0]), "r"(a[1]), "r"(a[2]), "r"(a[3]), "r"(b[0]), "r"(b[1]));
}

// ---------------- prep: coalesced transposed fp16 weight tiles --------------
__global__ void prep_all(const float* __restrict__ W1, __half* __restrict__ o1,
                         const float* __restrict__ W2, __half* __restrict__ o2,
                         const float* __restrict__ W3, __half* __restrict__ o3)
{
    __shared__ __half t[32][72];   // 144B row stride, 16B-aligned rows
    int b = blockIdx.x;
    const float* W; __half* o; int K, N, ldw, tn, tc;
    if (b < 160)      {          W = W1; o = o1; K = K1; N = H1; ldw = K1P; tn = b % 8; tc = b / 8; }
    else if (b < 176) { b -= 160; W = W2; o = o2; K = H1; N = H2; ldw = H1;  tn = b % 4; tc = b / 4; }
    else              { b -= 176; W = W3; o = o3; K = H2; N = H3; ldw = H2;  tn = b % 2; tc = b / 2; }
    const int n0 = tn * 32, c0 = tc * 64;
    const int lx = threadIdx.x & 31, ly = threadIdx.x >> 5;  // 256 threads
    #pragma unroll
    for (int cc = ly; cc < 64; cc += 8) {
        int c = c0 + cc;
        float v = (c < K) ? W[(size_t)c * N + n0 + lx] : 0.0f;  // coalesced read
        t[lx][cc] = __float2half(v);
    }
    __syncthreads();
    const int rn = threadIdx.x >> 3;
    const int rc = (threadIdx.x & 7) * 8;
    *reinterpret_cast<uint4*>(o + (size_t)(n0 + rn) * ldw + c0 + rc) =
        *reinterpret_cast<const uint4*>(&t[rn][rc]);            // coalesced write
}

// 8 fp32 values of one feature at d in [q*8, q*8+8)
struct A8 { float4 a, b; };

// ---------------- megakernel: gather + FM + full MLP + head ----------------
// 512 threads, mainloop warp grid 2x8, warp tile 64x32.
// Chunk body reordered vs R9: gathered values are stored to smem BEFORE the
// MMA block (releasing 16 fp32 registers across it). LDG latency still hidden
// by cp_wait + barrier + B cp.async issue.
__global__ __launch_bounds__(512)
void mega_mlp(const int*   __restrict__ x_cat,
              const float* __restrict__ x_num,
              const float* __restrict__ emb0,
              const float* __restrict__ emb1,
              const float* __restrict__ num_bias,
              const float* __restrict__ num_emb,
              const __half* __restrict__ w1t,
              const __half* __restrict__ w2t,
              const __half* __restrict__ w3t,
              const float* __restrict__ b1,
              const float* __restrict__ b2,
              const float* __restrict__ b3,
              const float* __restrict__ Wc, const float* __restrict__ bc,
              const float* __restrict__ Wo, const float* __restrict__ bo,
              float* __restrict__ out)
{
    constexpr int THREADS = 512;
    constexpr int lda     = K1P;
    constexpr int nchunks = K1P / 64;          // 20 (2 features per chunk)

    extern __shared__ unsigned char smem[];
    const uint32_t sbase = smem_to_u32(smem);

    const int tid = threadIdx.x;
    const int wid = tid >> 5;
    const int lid = tid & 31;
    const int mrow0 = blockIdx.y * 128;

    int*   s_ids  = reinterpret_cast<int*>(smem + SM_IDS);
    float* s_xnum = reinterpret_cast<float*>(smem + SM_XNUM);
    float* s_nemb = reinterpret_cast<float*>(smem + SM_NEMB);
    float* s_linp = reinterpret_cast<float*>(smem + SM_LINP);
    float* s_fmp  = reinterpret_cast<float*>(smem + SM_FMP);

    // ---------- B (W1') pipeline ----------
    const int b_r = tid >> 3, b_c = tid & 7;   // row, 16B chunk
    const uint32_t bsm_off = (uint32_t)b_r * ROWB + (uint32_t)b_c * 16;
    const __half* wrow = w1t + (size_t)b_r * lda + b_c * 8;
    auto issue_B = [&](int c, int buf) {
        const int kc = c * 64;
        uint32_t Bs = sbase + buf * STAGE + A_BYTES;
        #pragma unroll
        for (int i = 0; i < 4; i++)
            cp_async16(Bs + bsm_off + i * 64 * ROWB, wrow + (size_t)i * 64 * lda + kc);
    };

    // ---------- A gather mapping: r = tid>>2 (128 rows), q = tid&3 ----------
    const int g_r = tid >> 2;
    const int g_q = tid & 3;

    // FM accumulators: this thread sees ALL features at its 8 d-positions
    float fmsum[8] = {0, 0, 0, 0, 0, 0, 0, 0};
    float sqtot = 0.0f;

    auto fetch_feat = [&](int f) -> A8 {
        A8 o;
        if (f < F_CAT) {
            int id = s_ids[g_r * F_CAT + f];
            const float4* p = reinterpret_cast<const float4*>(
                emb1 + ((size_t)f * VOCAB + id) * 32 + g_q * 8);
            o.a = p[0]; o.b = p[1];
        } else if (f < F_CAT + N_NUM) {
            int n = f - F_CAT;
            float xv = s_xnum[g_r * N_NUM + n];
            const float4* p = reinterpret_cast<const float4*>(s_nemb + n * 32 + g_q * 8);
            float4 e0 = p[0], e1 = p[1];
            o.a = make_float4(xv * e0.x, xv * e0.y, xv * e0.z, xv * e0.w);
            o.b = make_float4(xv * e1.x, xv * e1.y, xv * e1.z, xv * e1.w);
        } else {
            o.a = make_float4(0, 0, 0, 0);
            o.b = make_float4(0, 0, 0, 0);
        }
        return o;
    };
    // accumulate FM + convert + store 16B into A stage (half = 0 for f0, 1 for f1)
    auto store_feat = [&](const A8& v, int buf, int half) {
        fmsum[0] += v.a.x; fmsum[1] += v.a.y; fmsum[2] += v.a.z; fmsum[3] += v.a.w;
        fmsum[4] += v.b.x; fmsum[5] += v.b.y; fmsum[6] += v.b.z; fmsum[7] += v.b.w;
        sqtot += v.a.x * v.a.x + v.a.y * v.a.y + v.a.z * v.a.z + v.a.w * v.a.w
               + v.b.x * v.b.x + v.b.y * v.b.y + v.b.z * v.b.z + v.b.w * v.b.w;
        __half2 h0 = __floats2half2_rn(v.a.x, v.a.y);
        __half2 h1 = __floats2half2_rn(v.a.z, v.a.w);
        __half2 h2 = __floats2half2_rn(v.b.x, v.b.y);
        __half2 h3 = __floats2half2_rn(v.b.z, v.b.w);
        uint4 u;
        u.x = *reinterpret_cast<uint32_t*>(&h0);
        u.y = *reinterpret_cast<uint32_t*>(&h1);
        u.z = *reinterpret_cast<uint32_t*>(&h2);
        u.w = *reinterpret_cast<uint32_t*>(&h3);
        *reinterpret_cast<uint4*>(smem + buf * STAGE + g_r * ROWB + half * 64 + g_q * 16) = u;
    };

    // ---------- prologue ----------
    issue_B(0, 0); cp_commit();
    issue_B(1, 1); cp_commit();

    // preload ids / x_num / num_emb
    for (int i = tid; i < 128 * F_CAT; i += THREADS)
        s_ids[i] = x_cat[(size_t)(mrow0 + i / F_CAT) * F_CAT + (i % F_CAT)];
    for (int i = tid; i < 128 * N_NUM; i += THREADS)
        s_xnum[i] = x_num[(size_t)(mrow0 + i / N_NUM) * N_NUM + (i % N_NUM)];
    for (int i = tid; i < N_NUM * 32; i += THREADS)
        s_nemb[i] = num_emb[i];
    __syncthreads();

    // linear-term partials (4 per row)
    {
        float lp = 0.0f;
        for (int f = g_q; f < F_CAT; f += 4)
            lp += __ldg(emb0 + (size_t)f * VOCAB + s_ids[g_r * F_CAT + f]);
        if (g_q == 0) {
            #pragma unroll
            for (int n = 0; n < N_NUM; n++)
                lp += s_xnum[g_r * N_NUM + n] * __ldg(num_bias + n);
        }
        s_linp[g_r * 4 + g_q] = lp;
    }
    // stage A chunks 0 and 1
    {
        A8 v0 = fetch_feat(0), v1 = fetch_feat(1);
        store_feat(v0, 0, 0); store_feat(v1, 0, 1);
        A8 v2 = fetch_feat(2), v3 = fetch_feat(3);
        store_feat(v2, 1, 0); store_feat(v3, 1, 1);
    }
    __syncthreads();

    // ---------- mainloop: warp grid 2x8, warp tile 64x32 ----------
    float acc[4][4][4];
    #pragma unroll
    for (int i = 0; i < 4; i++)
        #pragma unroll
        for (int j = 0; j < 4; j++)
            #pragma unroll
            for (int k = 0; k < 4; k++) acc[i][j][k] = 0.0f;

    const int wm = wid >> 3;                   // 0..1
    const int wn = wid & 7;                    // 0..7
    const uint32_t a_lane = (uint32_t)(wm * 64 + (lid & 15)) * ROWB + (uint32_t)(lid >> 4) * 16;
    const uint32_t b_lane = (uint32_t)(wn * 32 + (lid & 15)) * ROWB + (uint32_t)(lid >> 4) * 16;

    for (int c = 0; c < nchunks; c++) {
        const int buf = c % 3;
        const bool has = (c + 2 < nchunks);
        const int nbuf = (c + 2) % 3;

        // issue gather LDGs early — they complete during cp_wait + barrier
        A8 v0, v1;
        if (has) { v0 = fetch_feat(2 * (c + 2)); v1 = fetch_feat(2 * (c + 2) + 1); }

        cp_wait<1>();
        __syncthreads();

        if (has) issue_B(c + 2, nbuf);
        cp_commit();

        // store gathered A BEFORE the MMA block: the 16 fp32 regs die here,
        // giving ptxas slack to pipeline the LDSM/HMMA chains below.
        // (buffer nbuf's A region was last read at iter c-1; the barrier
        //  above orders those reads before these writes.)
        if (has) { store_feat(v0, nbuf, 0); store_feat(v1, nbuf, 1); }

        const uint32_t As = sbase + buf * STAGE + a_lane;
        const uint32_t Bs = sbase + buf * STAGE + A_BYTES + b_lane;
        #pragma unroll
        for (int kk = 0; kk < 4; kk++) {
            uint32_t bf_[4][2];
            #pragma unroll
            for (int j = 0; j < 2; j++) {
                uint32_t r0, r1, r2, r3;
                ldsm_x4(r0, r1, r2, r3, Bs + j * 16 * ROWB + kk * 32);
                bf_[j * 2 + 0][0] = r0; bf_[j * 2 + 0][1] = r2;
                bf_[j * 2 + 1][0] = r1; bf_[j * 2 + 1][1] = r3;
            }
            uint32_t af[4][4];
            #pragma unroll
            for (int mi = 0; mi < 4; mi++)
                ldsm_x4(af[mi][0], af[mi][1], af[mi][2], af[mi][3],
                        As + mi * 16 * ROWB + kk * 32);
            #pragma unroll
            for (int mi = 0; mi < 4; mi++)
                #pragma unroll
                for (int ni = 0; ni < 4; ni++)
                    mma16816(acc[mi][ni], af[mi], bf_[ni]);
        }
    }

    // FM partials (all features seen; finalize per thread)
    {
        float p = -sqtot;
        #pragma unroll
        for (int j = 0; j < 8; j++) p += fmsum[j] * fmsum[j];
        s_fmp[g_r * 4 + g_q] = p;
    }

    cp_wait<0>();
    __syncthreads();

    // prefetch W2' (128 x 256 -> stride 528) and W3' (64 x 128 -> stride 272)
    {
        #pragma unroll
        for (int i = 0; i < 8; i++) {
            int idx = tid + i * THREADS;               // 4096 chunks
            int row = idx >> 5, ch = idx & 31;
            cp_async16(sbase + SM_W2 + row * 528 + ch * 16,
                       w2t + (size_t)row * H1 + ch * 8);
        }
        #pragma unroll
        for (int i = 0; i < 2; i++) {
            int idx = tid + i * THREADS;               // 1024 chunks
            int row = idx >> 4, ch = idx & 15;
            cp_async16(sbase + SM_W3 + row * 272 + ch * 16,
                       w3t + (size_t)row * H2 + ch * 8);
        }
        cp_commit();
    }
    {
        float* hw = reinterpret_cast<float*>(smem + SM_HEAD);
        if (tid < 66)  hw[tid] = Wc[tid];
        if (tid >= 256 && tid < 322) hw[66 + tid - 256] = Wo[tid - 256];
    }

    // h1 fragments -> smem (relu + b1)
    {
        __half* h1p = reinterpret_cast<__half*>(smem + SM_H1);
        #pragma unroll
        for (int mi = 0; mi < 4; mi++) {
            #pragma unroll
            for (int ni = 0; ni < 4; ni++) {
                const int m0 = wm * 64 + mi * 16 + (lid >> 2);
                const int n0 = wn * 32 + ni * 8 + (lid & 3) * 2;
                const float c0 = __ldg(&b1[n0]);
                const float c1 = __ldg(&b1[n0 + 1]);
                __half2 p0, p1;
                p0.x = __float2half(fmaxf(acc[mi][ni][0] + c0, 0.0f));
                p0.y = __float2half(fmaxf(acc[mi][ni][1] + c1, 0.0f));
                p1.x = __float2half(fmaxf(acc[mi][ni][2] + c0, 0.0f));
                p1.y = __float2half(fmaxf(acc[mi][ni][3] + c1, 0.0f));
                *reinterpret_cast<__half2*>(&h1p[m0 * 264 + n0]) = p0;
                *reinterpret_cast<__half2*>(&h1p[(m0 + 8) * 264 + n0]) = p1;
            }
        }
    }
    cp_wait<0>();
    __syncthreads();

    // ---------- stage 2: h2 = relu(h1 @ W2 + b2), K=256 ----------
    {
        const int wm2 = wid >> 3;
        const int wn2 = wid & 7;
        const uint32_t a2 = sbase + SM_H1 +
            (uint32_t)(wm2 * 64 + (lid & 15)) * 528 + (uint32_t)(lid >> 4) * 16;
        const uint32_t b2s = sbase + SM_W2 +
            (uint32_t)(wn2 * 16 + (lid & 15)) * 528 + (uint32_t)(lid >> 4) * 16;

        float acc2[4][2][4];
        #pragma unroll
        for (int i = 0; i < 4; i++)
            #pragma unroll
            for (int j = 0; j < 2; j++)
                #pragma unroll
                for (int k = 0; k < 4; k++) acc2[i][j][k] = 0.0f;

        #pragma unroll
        for (int kk = 0; kk < 16; kk++) {
            uint32_t r0, r1, r2, r3;
            ldsm_x4(r0, r1, r2, r3, b2s + kk * 32);
            uint32_t bf0[2] = {r0, r2};
            uint32_t bf1[2] = {r1, r3};
            #pragma unroll
            for (int mi = 0; mi < 4; mi++) {
                uint32_t af[4];
                ldsm_x4(af[0], af[1], af[2], af[3], a2 + mi * 16 * 528 + kk * 32);
                mma16816(acc2[mi][0], af, bf0);
                mma16816(acc2[mi][1], af, bf1);
            }
        }

        __half* h2p = reinterpret_cast<__half*>(smem + SM_H2);
        #pragma unroll
        for (int mi = 0; mi < 4; mi++) {
            #pragma unroll
            for (int ni = 0; ni < 2; ni++) {
                const int m0 = wm2 * 64 + mi * 16 + (lid >> 2);
                const int n0 = wn2 * 16 + ni * 8 + (lid & 3) * 2;
                const float c0 = __ldg(&b2[n0]);
                const float c1 = __ldg(&b2[n0 + 1]);
                __half2 p0, p1;
                p0.x = __float2half(fmaxf(acc2[mi][ni][0] + c0, 0.0f));
                p0.y = __float2half(fmaxf(acc2[mi][ni][1] + c1, 0.0f));
                p1.x = __float2half(fmaxf(acc2[mi][ni][2] + c0, 0.0f));
                p1.y = __float2half(fmaxf(acc2[mi][ni][3] + c1, 0.0f));
                *reinterpret_cast<__half2*>(&h2p[m0 * 136 + n0]) = p0;
                *reinterpret_cast<__half2*>(&h2p[(m0 + 8) * 136 + n0]) = p1;
            }
        }
    }
    __syncthreads();

    // ---------- stage 3: h3 = relu(h2 @ W3 + b3), K=128 ----------
    {
        const int wm3 = wid >> 2;
        const int wn3 = wid & 3;
        const uint32_t a3 = sbase + SM_H2 +
            (uint32_t)(wm3 * 32 + (lid & 15)) * 272 + (uint32_t)(lid >> 4) * 16;
        const uint32_t b3s = sbase + SM_W3 +
            (uint32_t)(wn3 * 16 + (lid & 15)) * 272 + (uint32_t)(lid >> 4) * 16;

        float acc3[2][2][4];
        #pragma unroll
        for (int i = 0; i < 2; i++)
            #pragma unroll
            for (int j = 0; j < 2; j++)
                #pragma unroll
                for (int k = 0; k < 4; k++) acc3[i][j][k] = 0.0f;

        #pragma unroll
        for (int kk = 0; kk < 8; kk++) {
            uint32_t r0, r1, r2, r3;
            ldsm_x4(r0, r1, r2, r3, b3s + kk * 32);
            uint32_t bf0[2] = {r0, r2};
            uint32_t bf1[2] = {r1, r3};
            #pragma unroll
            for (int mi = 0; mi < 2; mi++) {
                uint32_t af[4];
                ldsm_x4(af[0], af[1], af[2], af[3], a3 + mi * 16 * 272 + kk * 32);
                mma16816(acc3[mi][0], af, bf0);
                mma16816(acc3[mi][1], af, bf1);
            }
        }

        float* h3p = reinterpret_cast<float*>(smem + SM_H3);
        #pragma unroll
        for (int mi = 0; mi < 2; mi++) {
            #pragma unroll
            for (int ni = 0; ni < 2; ni++) {
                const int m0 = wm3 * 32 + mi * 16 + (lid >> 2);
                const int n0 = wn3 * 16 + ni * 8 + (lid & 3) * 2;
                const float c0 = __ldg(&b3[n0]);
                const float c1 = __ldg(&b3[n0 + 1]);
                *reinterpret_cast<float2*>(&h3p[m0 * 68 + n0]) = make_float2(
                    fmaxf(acc3[mi][ni][0] + c0, 0.0f), fmaxf(acc3[mi][ni][1] + c1, 0.0f));
                *reinterpret_cast<float2*>(&h3p[(m0 + 8) * 68 + n0]) = make_float2(
                    fmaxf(acc3[mi][ni][2] + c0, 0.0f), fmaxf(acc3[mi][ni][3] + c1, 0.0f));
            }
        }
    }
    __syncthreads();

    // ---------- head ----------
    if (tid < 128) {
        const float* h3p = reinterpret_cast<const float*>(smem + SM_H3) + tid * 68;
        const float* hw  = reinterpret_cast<const float*>(smem + SM_HEAD);
        float dc = 0.0f, dw = 0.0f;
        #pragma unroll
        for (int c = 0; c < H3; c++) {
            float v = h3p[c];
            dc += v * hw[c];
            dw += v * hw[66 + c];
        }
        const float l = s_linp[tid * 4] + s_linp[tid * 4 + 1]
                      + s_linp[tid * 4 + 2] + s_linp[tid * 4 + 3];
        const float f = 0.5f * (s_fmp[tid * 4] + s_fmp[tid * 4 + 1]
                              + s_fmp[tid * 4 + 2] + s_fmp[tid * 4 + 3]);
        const int r = mrow0 + tid;
        out[r]          = dc + l * hw[64] + f * hw[65] + __ldg(&bc[0]);
        out[B_ROWS + r] = dw + l * hw[66 + 64] + f * hw[66 + 65] + __ldg(&bo[0]);
    }
}

// ---------------- launch ----------------
extern "C" void kernel_launch(void* const* d_in, const int* in_sizes, int n_in,
                              void* d_out, int out_size)
{
    const int*   x_cat    = (const int*)  d_in[0];
    const float* x_num    = (const float*)d_in[1];
    const float* emb0     = (const float*)d_in[2];
    const float* emb1     = (const float*)d_in[3];
    const float* num_bias = (const float*)d_in[4];
    const float* num_emb  = (const float*)d_in[5];
    const float* W1 = (const float*)d_in[6];
    const float* b1 = (const float*)d_in[7];
    const float* W2 = (const float*)d_in[8];
    const float* b2 = (const float*)d_in[9];
    const float* W3 = (const float*)d_in[10];
    const float* b3 = (const float*)d_in[11];
    const float* Wc = (const float*)d_in[12];
    const float* bc = (const float*)d_in[13];
    const float* Wo = (const float*)d_in[14];
    const float* bo = (const float*)d_in[15];
    float* out = (float*)d_out;

    unsigned char* base = nullptr;
    cudaGetSymbolAddress((void**)&base, g_scratch);
    __half* w1t = (__half*)(base + OFF_W1T);
    __half* w2t = (__half*)(base + OFF_W2T);
    __half* w3t = (__half*)(base + OFF_W3T);

    cudaFuncSetAttribute(mega_mlp,
                         cudaFuncAttributeMaxDynamicSharedMemorySize, SMEM_MEGA);

    // 0) weight prep: 160 + 16 + 4 transpose tiles (coalesced)
    prep_all<<<180, 256>>>(W1, w1t, W2, w2t, W3, w3t);

    // 1) fused gather + FM + MLP + head
    mega_mlp<<<dim3(1, B_ROWS / 128), 512, SMEM_MEGA>>>(
        x_cat, x_num, emb0, emb1, num_bias, num_emb,
        w1t, w2t, w3t, b1, b2, b3, Wc, bc, Wo, bo, out);
}